// round 6
// baseline (speedup 1.0000x reference)
#include <cuda_runtime.h>
#include <cuda_bf16.h>
#include <stdint.h>
#include <math.h>

// Problem constants (fixed by the dataset)
#define N_TOK 16384
#define DIM   512

// GEMM tiling
#define BM 128
#define BN 128
#define BK 32
#define KT (DIM / BK)      // 16 k-tiles
#define PAD 8
#define LDS (BK + PAD)     // 40 bf16 elements per smem row (80B: conflict-free for ldmatrix)

// ---------------- device scratch (no allocations allowed) ----------------
__device__ __nv_bfloat16 g_nA[(size_t)N_TOK * DIM];   // normalized image emb (bf16)
__device__ __nv_bfloat16 g_nB[(size_t)N_TOK * DIM];   // normalized profile emb (bf16)
__device__ float g_part[(N_TOK / BM) * (N_TOK / BN)]; // per-CTA softplus partials (16384)
__device__ float g_diag[N_TOK / 8];                   // per-CTA diagonal partials (2048)

// ---------------- helpers ----------------
__device__ __forceinline__ uint32_t smem_u32(const void* p) {
    return (uint32_t)__cvta_generic_to_shared(p);
}

__device__ __forceinline__ void cp_async16(uint32_t dst, const void* src) {
    asm volatile("cp.async.cg.shared.global [%0], [%1], 16;\n" :: "r"(dst), "l"(src));
}
__device__ __forceinline__ void cp_commit() {
    asm volatile("cp.async.commit_group;\n" ::: "memory");
}
__device__ __forceinline__ void cp_wait_all() {
    asm volatile("cp.async.wait_group 0;\n" ::: "memory");
}

__device__ __forceinline__ void ldm_x4(uint32_t& r0, uint32_t& r1, uint32_t& r2, uint32_t& r3,
                                       uint32_t addr) {
    asm volatile("ldmatrix.sync.aligned.m8n8.x4.shared.b16 {%0,%1,%2,%3}, [%4];\n"
                 : "=r"(r0), "=r"(r1), "=r"(r2), "=r"(r3) : "r"(addr));
}

__device__ __forceinline__ void mma_bf16(float* d, const uint32_t* a, const uint32_t* b) {
    asm volatile(
        "mma.sync.aligned.m16n8k16.row.col.f32.bf16.bf16.f32 "
        "{%0,%1,%2,%3}, {%4,%5,%6,%7}, {%8,%9}, {%0,%1,%2,%3};\n"
        : "+f"(d[0]), "+f"(d[1]), "+f"(d[2]), "+f"(d[3])
        : "r"(a[0]), "r"(a[1]), "r"(a[2]), "r"(a[3]), "r"(b[0]), "r"(b[1]));
}

// softplus(x) = log(1+exp(x)); data sits near x ~ -10 so the series path dominates
__device__ __forceinline__ float softplus_f(float x) {
    float t = __expf(x);
    if (t < 9.765625e-4f) {                 // log1p(t) ~ t - t^2/2, rel err < 3e-7
        return fmaf(-0.5f * t, t, t);
    } else if (x > 80.0f) {
        return x;
    } else {
        return __logf(1.0f + t);
    }
}

// ---------------- kernel 1: L2-normalize rows, write bf16 ----------------
__global__ void normalize_kernel(const float* __restrict__ A, const float* __restrict__ B) {
    int row = blockIdx.x;
    const float* src = blockIdx.y ? B : A;
    __nv_bfloat16* dst = blockIdx.y ? g_nB : g_nA;
    const float* r = src + (size_t)row * DIM;
    int t = threadIdx.x;                       // 256 threads, 2 elements each
    float v0 = r[t], v1 = r[t + 256];
    float ss = v0 * v0 + v1 * v1;
    #pragma unroll
    for (int o = 16; o; o >>= 1) ss += __shfl_xor_sync(0xFFFFFFFFu, ss, o);
    __shared__ float sred[8];
    if ((t & 31) == 0) sred[t >> 5] = ss;
    __syncthreads();
    float tot = 0.f;
    #pragma unroll
    for (int i = 0; i < 8; i++) tot += sred[i];
    float inv = 1.0f / fmaxf(sqrtf(tot), 1e-12f);
    dst[(size_t)row * DIM + t]       = __float2bfloat16(v0 * inv);
    dst[(size_t)row * DIM + t + 256] = __float2bfloat16(v1 * inv);
}

// ---------------- kernel 2: fp32 diagonal logits, per-block partial ----------------
__global__ void diag_kernel(const float* __restrict__ A, const float* __restrict__ B,
                            const float* __restrict__ p_ls, const float* __restrict__ p_bias) {
    int wid = threadIdx.x >> 5, lane = threadIdx.x & 31;
    int row = blockIdx.x * 8 + wid;
    const float* a = A + (size_t)row * DIM;
    const float* b = B + (size_t)row * DIM;
    float sab = 0.f, saa = 0.f, sbb = 0.f;
    #pragma unroll 4
    for (int k = lane; k < DIM; k += 32) {
        float x = a[k], y = b[k];
        sab = fmaf(x, y, sab); saa = fmaf(x, x, saa); sbb = fmaf(y, y, sbb);
    }
    #pragma unroll
    for (int o = 16; o; o >>= 1) {
        sab += __shfl_xor_sync(0xFFFFFFFFu, sab, o);
        saa += __shfl_xor_sync(0xFFFFFFFFu, saa, o);
        sbb += __shfl_xor_sync(0xFFFFFFFFu, sbb, o);
    }
    __shared__ float sred[8];
    if (lane == 0) {
        float scale = expf(*p_ls);
        float dot = sab / (fmaxf(sqrtf(saa), 1e-12f) * fmaxf(sqrtf(sbb), 1e-12f));
        sred[wid] = fmaf(scale, dot, *p_bias);   // l_ii
    }
    __syncthreads();
    if (threadIdx.x == 0) {
        float s = 0.f;
        #pragma unroll
        for (int i = 0; i < 8; i++) s += sred[i];
        g_diag[blockIdx.x] = s;
    }
}

// ---------------- kernel 3: bf16 tensor-core GEMM + fused softplus reduction ----------------
__global__ void __launch_bounds__(256, 2)
gemm_softplus_kernel(const float* __restrict__ p_ls, const float* __restrict__ p_bias) {
    __shared__ __align__(16) __nv_bfloat16 sA[2][BM * LDS];
    __shared__ __align__(16) __nv_bfloat16 sB[2][BN * LDS];
    __shared__ float sred[8];

    const int tid  = threadIdx.x;
    const int wid  = tid >> 5;
    const int lane = tid & 31;
    const int bm = blockIdx.y * BM;
    const int bn = blockIdx.x * BN;

    const __nv_bfloat16* gA = g_nA + (size_t)bm * DIM;
    const __nv_bfloat16* gB = g_nB + (size_t)bn * DIM;

    // global->shared load mapping: 512 16B-chunks per tile, 2 per thread
    const int c0 = tid, c1 = tid + 256;
    const int r0 = c0 >> 2, k0c = (c0 & 3) * 8;
    const int r1 = c1 >> 2, k1c = (c1 & 3) * 8;

    const uint32_t saBase = smem_u32(&sA[0][0]);
    const uint32_t sbBase = smem_u32(&sB[0][0]);
    const uint32_t stageBytes = BM * LDS * sizeof(__nv_bfloat16);   // 10240

    // warp tile: 64 (M) x 32 (N)
    const int wm = (wid >> 2) * 64;
    const int wn = (wid & 3) * 32;

    // ldmatrix lane offsets (elements within a stage)
    const int sub = lane >> 3, rr = lane & 7;
    const int aLaneOff = (wm + (sub & 1) * 8 + rr) * LDS + ((sub >> 1) * 8);
    const int bLaneOff = (wn + (sub >> 1) * 8 + rr) * LDS + ((sub & 1) * 8);

    float acc[4][4][4];
    #pragma unroll
    for (int mt = 0; mt < 4; mt++)
        #pragma unroll
        for (int nt = 0; nt < 4; nt++)
            #pragma unroll
            for (int i = 0; i < 4; i++) acc[mt][nt][i] = 0.f;

    // ---- prologue: stage 0 ----
    {
        uint32_t da = saBase, db = sbBase;
        cp_async16(da + (uint32_t)(r0 * LDS + k0c) * 2, gA + (size_t)r0 * DIM + k0c);
        cp_async16(da + (uint32_t)(r1 * LDS + k1c) * 2, gA + (size_t)r1 * DIM + k1c);
        cp_async16(db + (uint32_t)(r0 * LDS + k0c) * 2, gB + (size_t)r0 * DIM + k0c);
        cp_async16(db + (uint32_t)(r1 * LDS + k1c) * 2, gB + (size_t)r1 * DIM + k1c);
        cp_commit();
    }
    cp_wait_all();
    __syncthreads();

    for (int kt = 0; kt < KT; kt++) {
        const int cur = kt & 1;
        if (kt + 1 < KT) {
            const int nk = (kt + 1) * BK;
            uint32_t da = saBase + (cur ^ 1) * stageBytes;
            uint32_t db = sbBase + (cur ^ 1) * stageBytes;
            cp_async16(da + (uint32_t)(r0 * LDS + k0c) * 2, gA + (size_t)r0 * DIM + nk + k0c);
            cp_async16(da + (uint32_t)(r1 * LDS + k1c) * 2, gA + (size_t)r1 * DIM + nk + k1c);
            cp_async16(db + (uint32_t)(r0 * LDS + k0c) * 2, gB + (size_t)r0 * DIM + nk + k0c);
            cp_async16(db + (uint32_t)(r1 * LDS + k1c) * 2, gB + (size_t)r1 * DIM + nk + k1c);
            cp_commit();
        }

        const uint32_t aSt = saBase + cur * stageBytes;
        const uint32_t bSt = sbBase + cur * stageBytes;
        #pragma unroll
        for (int ks = 0; ks < 2; ks++) {
            uint32_t a[4][4], b[4][2];
            #pragma unroll
            for (int mt = 0; mt < 4; mt++) {
                uint32_t addr = aSt + (uint32_t)(aLaneOff + mt * 16 * LDS + ks * 16) * 2;
                ldm_x4(a[mt][0], a[mt][1], a[mt][2], a[mt][3], addr);
            }
            #pragma unroll
            for (int p = 0; p < 2; p++) {
                uint32_t addr = bSt + (uint32_t)(bLaneOff + p * 16 * LDS + ks * 16) * 2;
                ldm_x4(b[2 * p][0], b[2 * p][1], b[2 * p + 1][0], b[2 * p + 1][1], addr);
            }
            #pragma unroll
            for (int mt = 0; mt < 4; mt++)
                #pragma unroll
                for (int nt = 0; nt < 4; nt++)
                    mma_bf16(acc[mt][nt], a[mt], b[nt]);
        }

        if (kt + 1 < KT) cp_wait_all();
        __syncthreads();
    }

    // ---- fused epilogue: softplus + reduce ----
    const float scale = expf(*p_ls);
    const float bias  = *p_bias;
    float s = 0.f;
    #pragma unroll
    for (int mt = 0; mt < 4; mt++)
        #pragma unroll
        for (int nt = 0; nt < 4; nt++)
            #pragma unroll
            for (int i = 0; i < 4; i++) {
                float x = fmaf(acc[mt][nt][i], scale, bias);
                s += softplus_f(x);
            }
    #pragma unroll
    for (int o = 16; o; o >>= 1) s += __shfl_xor_sync(0xFFFFFFFFu, s, o);
    if (lane == 0) sred[wid] = s;
    __syncthreads();
    if (tid == 0) {
        float bsum = 0.f;
        #pragma unroll
        for (int i = 0; i < 8; i++) bsum += sred[i];
        g_part[blockIdx.y * gridDim.x + blockIdx.x] = bsum;
    }
}

// ---------------- kernel 4: final reduction ----------------
__global__ void finalize_kernel(float* __restrict__ out) {
    double s = 0.0;
    for (int i = threadIdx.x; i < (N_TOK / BM) * (N_TOK / BN); i += 256)
        s += (double)g_part[i];
    double d = 0.0;
    for (int i = threadIdx.x; i < N_TOK / 8; i += 256)
        d += (double)g_diag[i];
    s -= d;                                  // total = sum softplus(l) - sum diag l
    __shared__ double sm[256];
    sm[threadIdx.x] = s;
    __syncthreads();
    for (int o = 128; o; o >>= 1) {
        if (threadIdx.x < o) sm[threadIdx.x] += sm[threadIdx.x + o];
        __syncthreads();
    }
    if (threadIdx.x == 0) out[0] = (float)(sm[0] / (double)N_TOK);   // /bs, buckets=1
}

// ---------------- launch ----------------
extern "C" void kernel_launch(void* const* d_in, const int* in_sizes, int n_in,
                              void* d_out, int out_size) {
    const float* img  = (const float*)d_in[0];
    const float* prof = (const float*)d_in[1];
    const float* ls   = (const float*)d_in[2];
    const float* bias = (const float*)d_in[3];
    (void)in_sizes; (void)n_in; (void)out_size;

    normalize_kernel<<<dim3(N_TOK, 2), 256>>>(img, prof);
    diag_kernel<<<N_TOK / 8, 256>>>(img, prof, ls, bias);
    gemm_softplus_kernel<<<dim3(N_TOK / BN, N_TOK / BM), 256>>>(ls, bias);
    finalize_kernel<<<1, 256>>>((float*)d_out);
}